// round 1
// baseline (speedup 1.0000x reference)
#include <cuda_runtime.h>

// ---------------------------------------------------------------------------
// WaveNet forward, fp32, GB300. Shapes fixed by the problem.
// ---------------------------------------------------------------------------
#define TB   4          // batch
#define TSEQ 8192       // T
#define NC   128        // feature channels C
#define NR   64         // residual channels R
#define N2R  128        // 2R
#define NS   256        // skip channels S
#define NL   16         // layers
#define TT   128        // time tile per CTA
#define NTH  256        // threads per CTA
#define SQRT_HALF 0.70710678118654752f

// Scratch (device globals: allocation-free per harness rules)
__device__ float g_x[2][TB][NR][TSEQ];   // ping-pong residual stream (16 MB)
__device__ float g_skip[TB][NS][TSEQ];   // skip accumulator (32 MB)
__device__ float g_h[TB][NS][TSEQ];      // head intermediate (32 MB)

// ---------------------------------------------------------------------------
// Embedding: x0[b][r][t] = embed[tokens[b][t]][r]
// ---------------------------------------------------------------------------
__global__ void embed_kernel(const int* __restrict__ tokens,
                             const float* __restrict__ embed) {
    int t = blockIdx.x * blockDim.x + threadIdx.x;
    int b = blockIdx.y;
    int tok = tokens[b * TSEQ + t];
    const float* e = embed + tok * NR;
#pragma unroll 8
    for (int r = 0; r < NR; ++r)
        g_x[0][b][r][t] = e[r];
}

// ---------------------------------------------------------------------------
// cond = cond_W(2048x128) @ features(b,128,T) + cond_b  -> d_out cond region
// Tile: 128 rows x 128 cols, K=128. 256 threads, 8x8 regs/thread.
// ---------------------------------------------------------------------------
__global__ void __launch_bounds__(NTH)
cond_kernel(const float* __restrict__ features,
            const float* __restrict__ cond_W,
            const float* __restrict__ cond_b,
            float* __restrict__ cond_out) {
    extern __shared__ float sm[];
    float* sW = sm;             // [128][128]
    float* sF = sm + 128 * 128; // [128][128] (k-major)

    int tid = threadIdx.x;
    int t0 = blockIdx.x * TT;
    int o0 = blockIdx.y * 128;
    int b  = blockIdx.z;

    for (int i = tid; i < 4096; i += NTH) {           // 16384 floats as float4
        int row = i >> 5, c4 = i & 31;
        ((float4*)sW)[i] = *(const float4*)&cond_W[(o0 + row) * NC + c4 * 4];
    }
    for (int i = tid; i < 4096; i += NTH) {
        int k = i >> 5, c4 = i & 31;
        ((float4*)sF)[i] =
            *(const float4*)&features[((size_t)b * NC + k) * TSEQ + t0 + c4 * 4];
    }
    __syncthreads();

    int rg = tid >> 4, cg = tid & 15;
    float acc[8][8];
#pragma unroll
    for (int m = 0; m < 8; ++m)
#pragma unroll
        for (int j = 0; j < 8; ++j) acc[m][j] = 0.f;

    const float4* f4 = (const float4*)sF;
    for (int k = 0; k < 128; ++k) {
        float4 x0 = f4[k * 32 + cg * 2];
        float4 x1 = f4[k * 32 + cg * 2 + 1];
        float xv[8] = {x0.x, x0.y, x0.z, x0.w, x1.x, x1.y, x1.z, x1.w};
#pragma unroll
        for (int m = 0; m < 8; ++m) {
            float w = sW[(rg * 8 + m) * 128 + k];
#pragma unroll
            for (int j = 0; j < 8; ++j) acc[m][j] += w * xv[j];
        }
    }
#pragma unroll
    for (int m = 0; m < 8; ++m) {
        int o = o0 + rg * 8 + m;
        float bias = __ldg(&cond_b[o]);
        size_t off = ((size_t)b * 2048 + o) * TSEQ + t0 + cg * 8;
        *(float4*)&cond_out[off] =
            make_float4(acc[m][0] + bias, acc[m][1] + bias, acc[m][2] + bias, acc[m][3] + bias);
        *(float4*)&cond_out[off + 4] =
            make_float4(acc[m][4] + bias, acc[m][5] + bias, acc[m][6] + bias, acc[m][7] + bias);
    }
}

// ---------------------------------------------------------------------------
// One WaveNet layer: dilated conv -> write in_acts -> +cond -> gate ->
// skip accumulate -> residual update (skipped on last layer).
// Grid (T/TT, B), 256 threads. Dyn smem = 160 KB.
// ---------------------------------------------------------------------------
__global__ void __launch_bounds__(NTH)
layer_kernel(const float* __restrict__ dilate_W,
             const float* __restrict__ dilate_b,
             const float* __restrict__ res_W,
             const float* __restrict__ res_b,
             const float* __restrict__ skip_W,
             const float* __restrict__ skip_b,
             const float* __restrict__ cond_base,
             float* __restrict__ ia_base,
             int l, int d, int par) {
    extern __shared__ float sm[];
    float* sXp   = sm;          // [64][128]
    float* sXc   = sm + 8192;   // [64][128]
    float* sActs = sm + 16384;  // [64][128]
    float* sW    = sm + 24576;  // 16384 floats, reused per stage

    int tid = threadIdx.x;
    int t0  = blockIdx.x * TT;
    int b   = blockIdx.y;
    const float* xin = &g_x[par][b][0][0];
    float* xout      = &g_x[par ^ 1][b][0][0];

    // ---- stage loads: x tiles + dilate weights ----
    for (int i = tid; i < 2048; i += NTH) {     // sXc float4 copy
        int r = i >> 5, tq = i & 31;
        ((float4*)sXc)[i] = *(const float4*)&xin[r * TSEQ + t0 + tq * 4];
    }
    for (int i = tid; i < 8192; i += NTH) {     // sXp scalar (d may be odd)
        int r = i >> 7, t = i & 127;
        int tg = t0 - d + t;
        sXp[i] = (tg >= 0) ? xin[r * TSEQ + tg] : 0.0f;
    }
    {
        const float* gW = dilate_W + (size_t)l * (N2R * NR * 2);
        for (int i = tid; i < 4096; i += NTH)
            ((float4*)sW)[i] = ((const float4*)gW)[i];
    }
    __syncthreads();

    int rg = tid >> 4, cg = tid & 15;
    int tcol = t0 + cg * 8;

    // ---- stage 1: ia[128][TT] = W0@xprev + W1@xcur ----
    float acc[8][8];
#pragma unroll
    for (int m = 0; m < 8; ++m)
#pragma unroll
        for (int j = 0; j < 8; ++j) acc[m][j] = 0.f;

    int orow[8];
#pragma unroll
    for (int m = 0; m < 8; ++m) orow[m] = (m < 4) ? (rg * 4 + m) : (64 + rg * 4 + (m - 4));

    {
        const float4* xp4 = (const float4*)sXp;
        const float4* xc4 = (const float4*)sXc;
        for (int k = 0; k < 64; ++k) {
            float4 p0 = xp4[k * 32 + cg * 2], p1 = xp4[k * 32 + cg * 2 + 1];
            float4 c0 = xc4[k * 32 + cg * 2], c1 = xc4[k * 32 + cg * 2 + 1];
            float pv[8] = {p0.x, p0.y, p0.z, p0.w, p1.x, p1.y, p1.z, p1.w};
            float cv[8] = {c0.x, c0.y, c0.z, c0.w, c1.x, c1.y, c1.z, c1.w};
#pragma unroll
            for (int m = 0; m < 8; ++m) {
                float2 w = *(const float2*)&sW[(orow[m] * 64 + k) * 2];
#pragma unroll
                for (int j = 0; j < 8; ++j)
                    acc[m][j] = fmaf(w.y, cv[j], fmaf(w.x, pv[j], acc[m][j]));
            }
        }
    }

    // epilogue: +bias, write in_acts, read cond, a = ia + cond
#pragma unroll
    for (int m = 0; m < 8; ++m) {
        int o = orow[m];
        float bias = __ldg(&dilate_b[l * N2R + o]);
        size_t roff = ((size_t)(b * NL + l) * N2R + o) * TSEQ + tcol;
        float ia[8];
#pragma unroll
        for (int j = 0; j < 8; ++j) ia[j] = acc[m][j] + bias;
        *(float4*)&ia_base[roff]     = make_float4(ia[0], ia[1], ia[2], ia[3]);
        *(float4*)&ia_base[roff + 4] = make_float4(ia[4], ia[5], ia[6], ia[7]);
        float4 q0 = *(const float4*)&cond_base[roff];
        float4 q1 = *(const float4*)&cond_base[roff + 4];
        float qv[8] = {q0.x, q0.y, q0.z, q0.w, q1.x, q1.y, q1.z, q1.w};
#pragma unroll
        for (int j = 0; j < 8; ++j) acc[m][j] = ia[j] + qv[j];
    }

    // gated activation: acts[r] = tanh(a[r]) * sigmoid(a[r+64])
#pragma unroll
    for (int m = 0; m < 4; ++m) {
        float av[8];
#pragma unroll
        for (int j = 0; j < 8; ++j) {
            float th = tanhf(acc[m][j]);
            float sg = 0.5f * tanhf(0.5f * acc[m + 4][j]) + 0.5f;  // exact sigmoid identity
            av[j] = th * sg;
        }
        int r = rg * 4 + m;
        *(float4*)&sActs[r * 128 + cg * 8]     = make_float4(av[0], av[1], av[2], av[3]);
        *(float4*)&sActs[r * 128 + cg * 8 + 4] = make_float4(av[4], av[5], av[6], av[7]);
    }
    __syncthreads();

    // ---- stage 2: skip += skip_W(256x64) @ acts ----
    {
        const float* gSW = skip_W + (size_t)l * (NS * NR);
        for (int i = tid; i < 4096; i += NTH)
            ((float4*)sW)[i] = ((const float4*)gSW)[i];
    }
    __syncthreads();

    float* skp = &g_skip[b][0][0];
    const float4* a4 = (const float4*)sActs;
    for (int h = 0; h < 2; ++h) {
        float acc2[8][8];
#pragma unroll
        for (int m = 0; m < 8; ++m)
#pragma unroll
            for (int j = 0; j < 8; ++j) acc2[m][j] = 0.f;
        for (int k = 0; k < 64; ++k) {
            float4 a0 = a4[k * 32 + cg * 2], a1 = a4[k * 32 + cg * 2 + 1];
            float avv[8] = {a0.x, a0.y, a0.z, a0.w, a1.x, a1.y, a1.z, a1.w};
#pragma unroll
            for (int m = 0; m < 8; ++m) {
                float w = sW[(h * 128 + rg * 8 + m) * 64 + k];
#pragma unroll
                for (int j = 0; j < 8; ++j) acc2[m][j] += w * avv[j];
            }
        }
#pragma unroll
        for (int m = 0; m < 8; ++m) {
            int s = h * 128 + rg * 8 + m;
            float bias = __ldg(&skip_b[l * NS + s]);
            float* sp = skp + (size_t)s * TSEQ + tcol;
            float4 v0 = make_float4(acc2[m][0] + bias, acc2[m][1] + bias,
                                    acc2[m][2] + bias, acc2[m][3] + bias);
            float4 v1 = make_float4(acc2[m][4] + bias, acc2[m][5] + bias,
                                    acc2[m][6] + bias, acc2[m][7] + bias);
            if (l != 0) {
                float4 p0 = *(const float4*)sp;
                float4 p1 = *(const float4*)(sp + 4);
                v0.x += p0.x; v0.y += p0.y; v0.z += p0.z; v0.w += p0.w;
                v1.x += p1.x; v1.y += p1.y; v1.z += p1.z; v1.w += p1.w;
            }
            *(float4*)sp       = v0;
            *(float4*)(sp + 4) = v1;
        }
    }

    // ---- stage 3: residual update (layers 0..14; layer 15's x is unused) ----
    if (l < NL - 1) {
        __syncthreads();
        const float* gRW = res_W + (size_t)l * (NR * NR);
        for (int i = tid; i < 1024; i += NTH)
            ((float4*)sW)[i] = ((const float4*)gRW)[i];
        __syncthreads();

        float acc3[4][8];
#pragma unroll
        for (int m = 0; m < 4; ++m)
#pragma unroll
            for (int j = 0; j < 8; ++j) acc3[m][j] = 0.f;
        for (int k = 0; k < 64; ++k) {
            float4 a0 = a4[k * 32 + cg * 2], a1 = a4[k * 32 + cg * 2 + 1];
            float avv[8] = {a0.x, a0.y, a0.z, a0.w, a1.x, a1.y, a1.z, a1.w};
#pragma unroll
            for (int m = 0; m < 4; ++m) {
                float w = sW[(rg * 4 + m) * 64 + k];
#pragma unroll
                for (int j = 0; j < 8; ++j) acc3[m][j] += w * avv[j];
            }
        }
#pragma unroll
        for (int m = 0; m < 4; ++m) {
            int r = rg * 4 + m;
            float bias = __ldg(&res_b[l * NR + r]);
            float4 x0 = *(const float4*)&sXc[r * 128 + cg * 8];
            float4 x1 = *(const float4*)&sXc[r * 128 + cg * 8 + 4];
            float xv[8] = {x0.x, x0.y, x0.z, x0.w, x1.x, x1.y, x1.z, x1.w};
            float ov[8];
#pragma unroll
            for (int j = 0; j < 8; ++j)
                ov[j] = (acc3[m][j] + bias + xv[j]) * SQRT_HALF;
            size_t off = (size_t)r * TSEQ + tcol;
            *(float4*)&xout[off]     = make_float4(ov[0], ov[1], ov[2], ov[3]);
            *(float4*)&xout[off + 4] = make_float4(ov[4], ov[5], ov[6], ov[7]);
        }
    }
}

// ---------------------------------------------------------------------------
// Head: mode 0: g_h = relu(conv_out_W @ relu(g_skip))
//       mode 1: out  = shift_right(conv_end_W @ g_h)
// Grid (T/TT, 2, B). K=256 processed in 4 chunks of 64.
// ---------------------------------------------------------------------------
__global__ void __launch_bounds__(NTH)
head_kernel(const float* __restrict__ Wmat, float* __restrict__ outp, int mode) {
    extern __shared__ float sm[];
    float* sW  = sm;        // [128][64]
    float* sIn = sm + 8192; // [64][128]

    int tid = threadIdx.x;
    int t0 = blockIdx.x * TT;
    int o0 = blockIdx.y * 128;
    int b  = blockIdx.z;
    int rg = tid >> 4, cg = tid & 15;

    const float* in = (mode == 0) ? &g_skip[b][0][0] : &g_h[b][0][0];

    float acc[8][8];
#pragma unroll
    for (int m = 0; m < 8; ++m)
#pragma unroll
        for (int j = 0; j < 8; ++j) acc[m][j] = 0.f;

    for (int kc = 0; kc < 4; ++kc) {
        for (int i = tid; i < 2048; i += NTH) {        // W chunk [128][64]
            int row = i >> 4, c4 = i & 15;
            ((float4*)sW)[i] = *(const float4*)&Wmat[(o0 + row) * NS + kc * 64 + c4 * 4];
        }
        for (int i = tid; i < 2048; i += NTH) {        // input chunk [64][128]
            int k = i >> 5, c4 = i & 31;
            float4 v = *(const float4*)&in[(size_t)(kc * 64 + k) * TSEQ + t0 + c4 * 4];
            if (mode == 0) {   // relu(skip)
                v.x = fmaxf(v.x, 0.f); v.y = fmaxf(v.y, 0.f);
                v.z = fmaxf(v.z, 0.f); v.w = fmaxf(v.w, 0.f);
            }
            ((float4*)sIn)[i] = v;
        }
        __syncthreads();
        const float4* i4 = (const float4*)sIn;
        for (int k = 0; k < 64; ++k) {
            float4 x0 = i4[k * 32 + cg * 2], x1 = i4[k * 32 + cg * 2 + 1];
            float xv[8] = {x0.x, x0.y, x0.z, x0.w, x1.x, x1.y, x1.z, x1.w};
#pragma unroll
            for (int m = 0; m < 8; ++m) {
                float w = sW[(rg * 8 + m) * 64 + k];
#pragma unroll
                for (int j = 0; j < 8; ++j) acc[m][j] += w * xv[j];
            }
        }
        __syncthreads();
    }

#pragma unroll
    for (int m = 0; m < 8; ++m) {
        int o = o0 + rg * 8 + m;
        if (mode == 0) {
            float* hp = &g_h[b][o][t0 + cg * 8];
            *(float4*)hp = make_float4(fmaxf(acc[m][0], 0.f), fmaxf(acc[m][1], 0.f),
                                       fmaxf(acc[m][2], 0.f), fmaxf(acc[m][3], 0.f));
            *(float4*)(hp + 4) = make_float4(fmaxf(acc[m][4], 0.f), fmaxf(acc[m][5], 0.f),
                                             fmaxf(acc[m][6], 0.f), fmaxf(acc[m][7], 0.f));
        } else {
            size_t base = ((size_t)b * 256 + o) * TSEQ;
#pragma unroll
            for (int j = 0; j < 8; ++j) {
                int tc = t0 + cg * 8 + j;
                if (tc + 1 < TSEQ) outp[base + tc + 1] = acc[m][j];
            }
            if (blockIdx.x == 0 && cg == 0) outp[base] = 0.0f;  // shifted-in zero frame
        }
    }
}

// ---------------------------------------------------------------------------
extern "C" void kernel_launch(void* const* d_in, const int* in_sizes, int n_in,
                              void* d_out, int out_size) {
    const float* features   = (const float*)d_in[0];
    const int*   tokens     = (const int*)  d_in[1];
    const float* embed      = (const float*)d_in[2];
    const float* cond_W     = (const float*)d_in[3];
    const float* cond_b     = (const float*)d_in[4];
    const float* dilate_W   = (const float*)d_in[5];
    const float* dilate_b   = (const float*)d_in[6];
    const float* res_W      = (const float*)d_in[7];
    const float* res_b      = (const float*)d_in[8];
    const float* skip_W     = (const float*)d_in[9];
    const float* skip_b     = (const float*)d_in[10];
    const float* conv_out_W = (const float*)d_in[11];
    const float* conv_end_W = (const float*)d_in[12];

    float* outp      = (float*)d_out;                       // (B,256,T)
    float* ia_base   = outp + (size_t)TB * 256 * TSEQ;      // (B,L,128,T)
    float* cond_base = ia_base + (size_t)TB * NL * N2R * TSEQ;  // (B,L,128,T)

    static const int DILS[NL] = {1, 2, 4, 8, 16, 32, 64, 128, 256,
                                 1, 2, 4, 8, 16, 32, 64};

    cudaFuncSetAttribute(cond_kernel,  cudaFuncAttributeMaxDynamicSharedMemorySize, 131072);
    cudaFuncSetAttribute(layer_kernel, cudaFuncAttributeMaxDynamicSharedMemorySize, 163840);
    cudaFuncSetAttribute(head_kernel,  cudaFuncAttributeMaxDynamicSharedMemorySize, 65536);

    embed_kernel<<<dim3(TSEQ / 256, TB), 256>>>(tokens, embed);
    cond_kernel<<<dim3(TSEQ / TT, 16, TB), NTH, 131072>>>(features, cond_W, cond_b, cond_base);

    for (int l = 0; l < NL; ++l) {
        layer_kernel<<<dim3(TSEQ / TT, TB), NTH, 163840>>>(
            dilate_W, dilate_b, res_W, res_b, skip_W, skip_b,
            cond_base, ia_base, l, DILS[l], l & 1);
    }

    head_kernel<<<dim3(TSEQ / TT, 2, TB), NTH, 65536>>>(conv_out_W, nullptr, 0);
    head_kernel<<<dim3(TSEQ / TT, 2, TB), NTH, 65536>>>(conv_end_W, outp, 1);
}

// round 2
// speedup vs baseline: 1.0010x; 1.0010x over previous
#include <cuda_runtime.h>

// ---------------------------------------------------------------------------
// WaveNet forward, fp32, GB300. Shapes fixed by the problem.
// ---------------------------------------------------------------------------
#define TB   4          // batch
#define TSEQ 8192       // T
#define NC   128        // feature channels C
#define NR   64         // residual channels R
#define N2R  128        // 2R
#define NS   256        // skip channels S
#define NL   16         // layers
#define TT   128        // time tile per CTA
#define NTH  256        // threads per CTA
#define SQRT_HALF 0.70710678118654752f

// Scratch (device globals: allocation-free per harness rules)
__device__ float g_x[2][TB][NR][TSEQ];   // ping-pong residual stream (16 MB)
__device__ float g_skip[TB][NS][TSEQ];   // skip accumulator (32 MB)
__device__ float g_h[TB][NS][TSEQ];      // head intermediate (32 MB)

// ---------------------------------------------------------------------------
// Embedding: x0[b][r][t] = embed[tokens[b][t]][r]
// ---------------------------------------------------------------------------
__global__ void embed_kernel(const int* __restrict__ tokens,
                             const float* __restrict__ embed) {
    int t = blockIdx.x * blockDim.x + threadIdx.x;
    int b = blockIdx.y;
    int tok = tokens[b * TSEQ + t];
    const float* e = embed + tok * NR;
#pragma unroll 8
    for (int r = 0; r < NR; ++r)
        g_x[0][b][r][t] = e[r];
}

// ---------------------------------------------------------------------------
// cond = cond_W(2048x128) @ features(b,128,T) + cond_b  -> d_out cond region
// Tile: 128 rows x 128 cols, K=128. 256 threads, 8x8 regs/thread.
// ---------------------------------------------------------------------------
__global__ void __launch_bounds__(NTH)
cond_kernel(const float* __restrict__ features,
            const float* __restrict__ cond_W,
            const float* __restrict__ cond_b,
            float* __restrict__ cond_out) {
    extern __shared__ float sm[];
    float* sW = sm;             // [128][128]
    float* sF = sm + 128 * 128; // [128][128] (k-major)

    int tid = threadIdx.x;
    int t0 = blockIdx.x * TT;
    int o0 = blockIdx.y * 128;
    int b  = blockIdx.z;

    for (int i = tid; i < 4096; i += NTH) {           // 16384 floats as float4
        int row = i >> 5, c4 = i & 31;
        ((float4*)sW)[i] = *(const float4*)&cond_W[(o0 + row) * NC + c4 * 4];
    }
    for (int i = tid; i < 4096; i += NTH) {
        int k = i >> 5, c4 = i & 31;
        ((float4*)sF)[i] =
            *(const float4*)&features[((size_t)b * NC + k) * TSEQ + t0 + c4 * 4];
    }
    __syncthreads();

    int rg = tid >> 4, cg = tid & 15;
    float acc[8][8];
#pragma unroll
    for (int m = 0; m < 8; ++m)
#pragma unroll
        for (int j = 0; j < 8; ++j) acc[m][j] = 0.f;

    const float4* f4 = (const float4*)sF;
    for (int k = 0; k < 128; ++k) {
        float4 x0 = f4[k * 32 + cg * 2];
        float4 x1 = f4[k * 32 + cg * 2 + 1];
        float xv[8] = {x0.x, x0.y, x0.z, x0.w, x1.x, x1.y, x1.z, x1.w};
#pragma unroll
        for (int m = 0; m < 8; ++m) {
            float w = sW[(rg * 8 + m) * 128 + k];
#pragma unroll
            for (int j = 0; j < 8; ++j) acc[m][j] += w * xv[j];
        }
    }
#pragma unroll
    for (int m = 0; m < 8; ++m) {
        int o = o0 + rg * 8 + m;
        float bias = __ldg(&cond_b[o]);
        size_t off = ((size_t)b * 2048 + o) * TSEQ + t0 + cg * 8;
        *(float4*)&cond_out[off] =
            make_float4(acc[m][0] + bias, acc[m][1] + bias, acc[m][2] + bias, acc[m][3] + bias);
        *(float4*)&cond_out[off + 4] =
            make_float4(acc[m][4] + bias, acc[m][5] + bias, acc[m][6] + bias, acc[m][7] + bias);
    }
}

// ---------------------------------------------------------------------------
// One WaveNet layer: dilated conv -> write in_acts -> +cond -> gate ->
// skip accumulate -> residual update (skipped on last layer).
// Grid (T/TT, B), 256 threads. Dyn smem = 160 KB.
// ---------------------------------------------------------------------------
__global__ void __launch_bounds__(NTH)
layer_kernel(const float* __restrict__ dilate_W,
             const float* __restrict__ dilate_b,
             const float* __restrict__ res_W,
             const float* __restrict__ res_b,
             const float* __restrict__ skip_W,
             const float* __restrict__ skip_b,
             const float* __restrict__ cond_base,
             float* __restrict__ ia_base,
             int l, int d, int par) {
    extern __shared__ float sm[];
    float* sXp   = sm;          // [64][128]
    float* sXc   = sm + 8192;   // [64][128]
    float* sActs = sm + 16384;  // [64][128]
    float* sW    = sm + 24576;  // 16384 floats, reused per stage

    int tid = threadIdx.x;
    int t0  = blockIdx.x * TT;
    int b   = blockIdx.y;
    const float* xin = &g_x[par][b][0][0];
    float* xout      = &g_x[par ^ 1][b][0][0];

    // ---- stage loads: x tiles + dilate weights ----
    for (int i = tid; i < 2048; i += NTH) {     // sXc float4 copy
        int r = i >> 5, tq = i & 31;
        ((float4*)sXc)[i] = *(const float4*)&xin[r * TSEQ + t0 + tq * 4];
    }
    for (int i = tid; i < 8192; i += NTH) {     // sXp scalar (d may be odd)
        int r = i >> 7, t = i & 127;
        int tg = t0 - d + t;
        sXp[i] = (tg >= 0) ? xin[r * TSEQ + tg] : 0.0f;
    }
    {
        const float* gW = dilate_W + (size_t)l * (N2R * NR * 2);
        for (int i = tid; i < 4096; i += NTH)
            ((float4*)sW)[i] = ((const float4*)gW)[i];
    }
    __syncthreads();

    int rg = tid >> 4, cg = tid & 15;
    int tcol = t0 + cg * 8;

    // ---- stage 1: ia[128][TT] = W0@xprev + W1@xcur ----
    float acc[8][8];
#pragma unroll
    for (int m = 0; m < 8; ++m)
#pragma unroll
        for (int j = 0; j < 8; ++j) acc[m][j] = 0.f;

    int orow[8];
#pragma unroll
    for (int m = 0; m < 8; ++m) orow[m] = (m < 4) ? (rg * 4 + m) : (64 + rg * 4 + (m - 4));

    {
        const float4* xp4 = (const float4*)sXp;
        const float4* xc4 = (const float4*)sXc;
        for (int k = 0; k < 64; ++k) {
            float4 p0 = xp4[k * 32 + cg * 2], p1 = xp4[k * 32 + cg * 2 + 1];
            float4 c0 = xc4[k * 32 + cg * 2], c1 = xc4[k * 32 + cg * 2 + 1];
            float pv[8] = {p0.x, p0.y, p0.z, p0.w, p1.x, p1.y, p1.z, p1.w};
            float cv[8] = {c0.x, c0.y, c0.z, c0.w, c1.x, c1.y, c1.z, c1.w};
#pragma unroll
            for (int m = 0; m < 8; ++m) {
                float2 w = *(const float2*)&sW[(orow[m] * 64 + k) * 2];
#pragma unroll
                for (int j = 0; j < 8; ++j)
                    acc[m][j] = fmaf(w.y, cv[j], fmaf(w.x, pv[j], acc[m][j]));
            }
        }
    }

    // epilogue: +bias, write in_acts, read cond, a = ia + cond
#pragma unroll
    for (int m = 0; m < 8; ++m) {
        int o = orow[m];
        float bias = __ldg(&dilate_b[l * N2R + o]);
        size_t roff = ((size_t)(b * NL + l) * N2R + o) * TSEQ + tcol;
        float ia[8];
#pragma unroll
        for (int j = 0; j < 8; ++j) ia[j] = acc[m][j] + bias;
        *(float4*)&ia_base[roff]     = make_float4(ia[0], ia[1], ia[2], ia[3]);
        *(float4*)&ia_base[roff + 4] = make_float4(ia[4], ia[5], ia[6], ia[7]);
        float4 q0 = *(const float4*)&cond_base[roff];
        float4 q1 = *(const float4*)&cond_base[roff + 4];
        float qv[8] = {q0.x, q0.y, q0.z, q0.w, q1.x, q1.y, q1.z, q1.w};
#pragma unroll
        for (int j = 0; j < 8; ++j) acc[m][j] = ia[j] + qv[j];
    }

    // gated activation: acts[r] = tanh(a[r]) * sigmoid(a[r+64])
#pragma unroll
    for (int m = 0; m < 4; ++m) {
        float av[8];
#pragma unroll
        for (int j = 0; j < 8; ++j) {
            float th = tanhf(acc[m][j]);
            float sg = 0.5f * tanhf(0.5f * acc[m + 4][j]) + 0.5f;  // exact sigmoid identity
            av[j] = th * sg;
        }
        int r = rg * 4 + m;
        *(float4*)&sActs[r * 128 + cg * 8]     = make_float4(av[0], av[1], av[2], av[3]);
        *(float4*)&sActs[r * 128 + cg * 8 + 4] = make_float4(av[4], av[5], av[6], av[7]);
    }
    __syncthreads();

    // ---- stage 2: skip += skip_W(256x64) @ acts ----
    {
        const float* gSW = skip_W + (size_t)l * (NS * NR);
        for (int i = tid; i < 4096; i += NTH)
            ((float4*)sW)[i] = ((const float4*)gSW)[i];
    }
    __syncthreads();

    float* skp = &g_skip[b][0][0];
    const float4* a4 = (const float4*)sActs;
    for (int h = 0; h < 2; ++h) {
        float acc2[8][8];
#pragma unroll
        for (int m = 0; m < 8; ++m)
#pragma unroll
            for (int j = 0; j < 8; ++j) acc2[m][j] = 0.f;
        for (int k = 0; k < 64; ++k) {
            float4 a0 = a4[k * 32 + cg * 2], a1 = a4[k * 32 + cg * 2 + 1];
            float avv[8] = {a0.x, a0.y, a0.z, a0.w, a1.x, a1.y, a1.z, a1.w};
#pragma unroll
            for (int m = 0; m < 8; ++m) {
                float w = sW[(h * 128 + rg * 8 + m) * 64 + k];
#pragma unroll
                for (int j = 0; j < 8; ++j) acc2[m][j] += w * avv[j];
            }
        }
#pragma unroll
        for (int m = 0; m < 8; ++m) {
            int s = h * 128 + rg * 8 + m;
            float bias = __ldg(&skip_b[l * NS + s]);
            float* sp = skp + (size_t)s * TSEQ + tcol;
            float4 v0 = make_float4(acc2[m][0] + bias, acc2[m][1] + bias,
                                    acc2[m][2] + bias, acc2[m][3] + bias);
            float4 v1 = make_float4(acc2[m][4] + bias, acc2[m][5] + bias,
                                    acc2[m][6] + bias, acc2[m][7] + bias);
            if (l != 0) {
                float4 p0 = *(const float4*)sp;
                float4 p1 = *(const float4*)(sp + 4);
                v0.x += p0.x; v0.y += p0.y; v0.z += p0.z; v0.w += p0.w;
                v1.x += p1.x; v1.y += p1.y; v1.z += p1.z; v1.w += p1.w;
            }
            *(float4*)sp       = v0;
            *(float4*)(sp + 4) = v1;
        }
    }

    // ---- stage 3: residual update (layers 0..14; layer 15's x is unused) ----
    if (l < NL - 1) {
        __syncthreads();
        const float* gRW = res_W + (size_t)l * (NR * NR);
        for (int i = tid; i < 1024; i += NTH)
            ((float4*)sW)[i] = ((const float4*)gRW)[i];
        __syncthreads();

        float acc3[4][8];
#pragma unroll
        for (int m = 0; m < 4; ++m)
#pragma unroll
            for (int j = 0; j < 8; ++j) acc3[m][j] = 0.f;
        for (int k = 0; k < 64; ++k) {
            float4 a0 = a4[k * 32 + cg * 2], a1 = a4[k * 32 + cg * 2 + 1];
            float avv[8] = {a0.x, a0.y, a0.z, a0.w, a1.x, a1.y, a1.z, a1.w};
#pragma unroll
            for (int m = 0; m < 4; ++m) {
                float w = sW[(rg * 4 + m) * 64 + k];
#pragma unroll
                for (int j = 0; j < 8; ++j) acc3[m][j] += w * avv[j];
            }
        }
#pragma unroll
        for (int m = 0; m < 4; ++m) {
            int r = rg * 4 + m;
            float bias = __ldg(&res_b[l * NR + r]);
            float4 x0 = *(const float4*)&sXc[r * 128 + cg * 8];
            float4 x1 = *(const float4*)&sXc[r * 128 + cg * 8 + 4];
            float xv[8] = {x0.x, x0.y, x0.z, x0.w, x1.x, x1.y, x1.z, x1.w};
            float ov[8];
#pragma unroll
            for (int j = 0; j < 8; ++j)
                ov[j] = (acc3[m][j] + bias + xv[j]) * SQRT_HALF;
            size_t off = (size_t)r * TSEQ + tcol;
            *(float4*)&xout[off]     = make_float4(ov[0], ov[1], ov[2], ov[3]);
            *(float4*)&xout[off + 4] = make_float4(ov[4], ov[5], ov[6], ov[7]);
        }
    }
}

// ---------------------------------------------------------------------------
// Head: mode 0: g_h = relu(conv_out_W @ relu(g_skip))
//       mode 1: out  = shift_right(conv_end_W @ g_h)
// Grid (T/TT, 2, B). K=256 processed in 4 chunks of 64.
// ---------------------------------------------------------------------------
__global__ void __launch_bounds__(NTH)
head_kernel(const float* __restrict__ Wmat, float* __restrict__ outp, int mode) {
    extern __shared__ float sm[];
    float* sW  = sm;        // [128][64]
    float* sIn = sm + 8192; // [64][128]

    int tid = threadIdx.x;
    int t0 = blockIdx.x * TT;
    int o0 = blockIdx.y * 128;
    int b  = blockIdx.z;
    int rg = tid >> 4, cg = tid & 15;

    const float* in = (mode == 0) ? &g_skip[b][0][0] : &g_h[b][0][0];

    float acc[8][8];
#pragma unroll
    for (int m = 0; m < 8; ++m)
#pragma unroll
        for (int j = 0; j < 8; ++j) acc[m][j] = 0.f;

    for (int kc = 0; kc < 4; ++kc) {
        for (int i = tid; i < 2048; i += NTH) {        // W chunk [128][64]
            int row = i >> 4, c4 = i & 15;
            ((float4*)sW)[i] = *(const float4*)&Wmat[(o0 + row) * NS + kc * 64 + c4 * 4];
        }
        for (int i = tid; i < 2048; i += NTH) {        // input chunk [64][128]
            int k = i >> 5, c4 = i & 31;
            float4 v = *(const float4*)&in[(size_t)(kc * 64 + k) * TSEQ + t0 + c4 * 4];
            if (mode == 0) {   // relu(skip)
                v.x = fmaxf(v.x, 0.f); v.y = fmaxf(v.y, 0.f);
                v.z = fmaxf(v.z, 0.f); v.w = fmaxf(v.w, 0.f);
            }
            ((float4*)sIn)[i] = v;
        }
        __syncthreads();
        const float4* i4 = (const float4*)sIn;
        for (int k = 0; k < 64; ++k) {
            float4 x0 = i4[k * 32 + cg * 2], x1 = i4[k * 32 + cg * 2 + 1];
            float xv[8] = {x0.x, x0.y, x0.z, x0.w, x1.x, x1.y, x1.z, x1.w};
#pragma unroll
            for (int m = 0; m < 8; ++m) {
                float w = sW[(rg * 8 + m) * 64 + k];
#pragma unroll
                for (int j = 0; j < 8; ++j) acc[m][j] += w * xv[j];
            }
        }
        __syncthreads();
    }

#pragma unroll
    for (int m = 0; m < 8; ++m) {
        int o = o0 + rg * 8 + m;
        if (mode == 0) {
            float* hp = &g_h[b][o][t0 + cg * 8];
            *(float4*)hp = make_float4(fmaxf(acc[m][0], 0.f), fmaxf(acc[m][1], 0.f),
                                       fmaxf(acc[m][2], 0.f), fmaxf(acc[m][3], 0.f));
            *(float4*)(hp + 4) = make_float4(fmaxf(acc[m][4], 0.f), fmaxf(acc[m][5], 0.f),
                                             fmaxf(acc[m][6], 0.f), fmaxf(acc[m][7], 0.f));
        } else {
            size_t base = ((size_t)b * 256 + o) * TSEQ;
#pragma unroll
            for (int j = 0; j < 8; ++j) {
                int tc = t0 + cg * 8 + j;
                if (tc + 1 < TSEQ) outp[base + tc + 1] = acc[m][j];
            }
            if (blockIdx.x == 0 && cg == 0) outp[base] = 0.0f;  // shifted-in zero frame
        }
    }
}

// ---------------------------------------------------------------------------
extern "C" void kernel_launch(void* const* d_in, const int* in_sizes, int n_in,
                              void* d_out, int out_size) {
    const float* features   = (const float*)d_in[0];
    const int*   tokens     = (const int*)  d_in[1];
    const float* embed      = (const float*)d_in[2];
    const float* cond_W     = (const float*)d_in[3];
    const float* cond_b     = (const float*)d_in[4];
    const float* dilate_W   = (const float*)d_in[5];
    const float* dilate_b   = (const float*)d_in[6];
    const float* res_W      = (const float*)d_in[7];
    const float* res_b      = (const float*)d_in[8];
    const float* skip_W     = (const float*)d_in[9];
    const float* skip_b     = (const float*)d_in[10];
    const float* conv_out_W = (const float*)d_in[11];
    const float* conv_end_W = (const float*)d_in[12];

    float* outp      = (float*)d_out;                       // (B,256,T)
    float* ia_base   = outp + (size_t)TB * 256 * TSEQ;      // (B,L,128,T)
    float* cond_base = ia_base + (size_t)TB * NL * N2R * TSEQ;  // (B,L,128,T)

    static const int DILS[NL] = {1, 2, 4, 8, 16, 32, 64, 128, 256,
                                 1, 2, 4, 8, 16, 32, 64};

    cudaFuncSetAttribute(cond_kernel,  cudaFuncAttributeMaxDynamicSharedMemorySize, 131072);
    cudaFuncSetAttribute(layer_kernel, cudaFuncAttributeMaxDynamicSharedMemorySize, 163840);
    cudaFuncSetAttribute(head_kernel,  cudaFuncAttributeMaxDynamicSharedMemorySize, 65536);

    embed_kernel<<<dim3(TSEQ / 256, TB), 256>>>(tokens, embed);
    cond_kernel<<<dim3(TSEQ / TT, 16, TB), NTH, 131072>>>(features, cond_W, cond_b, cond_base);

    for (int l = 0; l < NL; ++l) {
        layer_kernel<<<dim3(TSEQ / TT, TB), NTH, 163840>>>(
            dilate_W, dilate_b, res_W, res_b, skip_W, skip_b,
            cond_base, ia_base, l, DILS[l], l & 1);
    }

    head_kernel<<<dim3(TSEQ / TT, 2, TB), NTH, 65536>>>(conv_out_W, nullptr, 0);
    head_kernel<<<dim3(TSEQ / TT, 2, TB), NTH, 65536>>>(conv_end_W, outp, 1);
}

// round 7
// speedup vs baseline: 1.2562x; 1.2549x over previous
#include <cuda_runtime.h>

#define TB 4
#define TSEQ 8192
#define NR 64
#define N2R 128
#define NS 256
#define NL 16
#define SQRT_HALF 0.70710678118654752f

__device__ float g_x[2][TB][NR][TSEQ];
__device__ float g_acts[NL][TB][NR][TSEQ];
__device__ float g_h1[TB][NS][TSEQ];
__device__ float g_h2[TB][NS][TSEQ];

__device__ __forceinline__ unsigned tf32r(float v) {
    unsigned u; asm("cvt.rna.tf32.f32 %0,%1;" : "=r"(u) : "f"(v)); return u;
}
__device__ __forceinline__ void mma8(float* d, uint4 a, uint2 b) {
    asm volatile(
        "mma.sync.aligned.m16n8k8.row.col.f32.tf32.tf32.f32 "
        "{%0,%1,%2,%3},{%4,%5,%6,%7},{%8,%9},{%0,%1,%2,%3};"
        : "+f"(d[0]), "+f"(d[1]), "+f"(d[2]), "+f"(d[3])
        : "r"(a.x), "r"(a.y), "r"(a.z), "r"(a.w), "r"(b.x), "r"(b.y));
}
// A-fragment slot for (time-in-tile tl, k<64); 8 k-chunks of 8
__device__ __forceinline__ int afrag(int tl, int k) {
    int r = tl & 15;
    return (((tl >> 4) * 8 + (k >> 3)) * 32 + (((r & 7) << 2) | (k & 3))) * 4
           + ((r >> 3) | (((k >> 2) & 1) << 1));
}
// B-fragment slot for (out-channel o, k<64)
__device__ __forceinline__ int bfrag(int o, int k) {
    return (((o >> 3) * 8 + (k >> 3)) * 32 + (((o & 7) << 2) | (k & 3))) * 2 + ((k >> 2) & 1);
}

// stage A tile [64 x 128] from src rows (stride TSEQ), time t0 (may be <0: zero pad)
template<int NTHR>
__device__ __forceinline__ void stageA(unsigned* AF, int lo, const float* __restrict__ src,
                                       int t0, int tid) {
    for (int i = tid; i < 64 * 128; i += NTHR) {
        int k = i >> 7, tl = i & 127, tg = t0 + tl;
        float v = (tg >= 0) ? src[(size_t)k * TSEQ + tg] : 0.f;
        unsigned h = tf32r(v);
        int off = afrag(tl, k);
        AF[off] = h; AF[lo + off] = tf32r(v - __uint_as_float(h));
    }
}
// stage B tile [O x 64]; element (o,k) at src[o*rstr + k*estr]
template<int NTHR>
__device__ __forceinline__ void stageB(unsigned* WF, int lo, const float* __restrict__ src,
                                       int O, int rstr, int estr, int tid) {
    for (int i = tid; i < O * 64; i += NTHR) {
        int o = i >> 6, k = i & 63;
        float v = src[(size_t)o * rstr + k * estr];
        unsigned h = tf32r(v);
        int off = bfrag(o, k);
        WF[off] = h; WF[lo + off] = tf32r(v - __uint_as_float(h));
    }
}
// warp tile: D[NT][4] += A(64k) x B, 3-mma tf32x2
template<int NT>
__device__ __forceinline__ void mma_tile(float (*D)[4], const unsigned* AF, int alo,
                                         const unsigned* WF, int wlo, int tt, int obase, int lane) {
#pragma unroll
    for (int kc = 0; kc < 8; ++kc) {
        uint4 ah = *(const uint4*)&AF[((tt * 8 + kc) * 32 + lane) * 4];
        uint4 al = *(const uint4*)&AF[alo + ((tt * 8 + kc) * 32 + lane) * 4];
#pragma unroll
        for (int nt = 0; nt < NT; ++nt) {
            int wb = (((obase + nt) * 8 + kc) * 32 + lane) * 2;
            uint2 bh = *(const uint2*)&WF[wb];
            uint2 bl = *(const uint2*)&WF[wlo + wb];
            mma8(D[nt], ah, bh);
            mma8(D[nt], al, bh);
            mma8(D[nt], ah, bl);
        }
    }
}

// ---------------------------------------------------------------------------
__global__ void embed_kernel(const int* __restrict__ tokens,
                             const float* __restrict__ embed) {
    int t = blockIdx.x * blockDim.x + threadIdx.x;
    int b = blockIdx.y;
    const float* e = embed + tokens[b * TSEQ + t] * NR;
#pragma unroll 8
    for (int r = 0; r < NR; ++r) g_x[0][b][r][t] = e[r];
}

// ---------------------------------------------------------------------------
__global__ void __launch_bounds__(512)
cond_kernel(const float* __restrict__ features, const float* __restrict__ cond_W,
            const float* __restrict__ cond_b, float* __restrict__ cond_out) {
    extern __shared__ unsigned smu[];
    unsigned* AF = smu;           // 16384
    unsigned* WF = smu + 16384;   // 16384
    float* sB = (float*)(smu + 32768);
    int tid = threadIdx.x, lane = tid & 31, warp = tid >> 5, tt = warp & 7, oh = warp >> 3;
    int t0 = blockIdx.x * 128, ob = blockIdx.y * 128, b = blockIdx.z;
    if (tid < 128) sB[tid] = cond_b[ob + tid];
    float D[8][4] = {};
    for (int ch = 0; ch < 2; ++ch) {
        __syncthreads();
        stageA<512>(AF, 8192, features + ((size_t)b * 128 + ch * 64) * TSEQ, t0, tid);
        stageB<512>(WF, 8192, cond_W + (size_t)ob * 128 + ch * 64, 128, 128, 1, tid);
        __syncthreads();
        mma_tile<8>(D, AF, 8192, WF, 8192, tt, oh * 8, lane);
    }
    int g = lane >> 2, tg = lane & 3, t1 = t0 + tt * 16 + g;
#pragma unroll
    for (int nt = 0; nt < 8; ++nt) {
        int o = oh * 64 + nt * 8 + tg * 2;
        size_t r0 = ((size_t)b * 2048 + ob + o) * TSEQ + t1, r1 = r0 + TSEQ;
        cond_out[r0] = D[nt][0] + sB[o];     cond_out[r1] = D[nt][1] + sB[o + 1];
        cond_out[r0 + 8] = D[nt][2] + sB[o]; cond_out[r1 + 8] = D[nt][3] + sB[o + 1];
    }
}

// ---------------------------------------------------------------------------
__global__ void __launch_bounds__(512)
layer_kernel(const float* __restrict__ dilate_W, const float* __restrict__ dilate_b,
             const float* __restrict__ res_W, const float* __restrict__ res_b,
             const float* __restrict__ cond_base, float* __restrict__ ia_base,
             int l, int d, int par) {
    extern __shared__ unsigned smu[];
    unsigned* XcF = smu;            // 16384
    unsigned* XpF = smu + 16384;    // 16384
    unsigned* WF  = smu + 32768;    // 16384
    float* sAfull  = (float*)smu;   // overlays XcF after GEMM1 (128x128)
    unsigned* ActsF = smu + 16384;  // overlays XpF
    unsigned* RWF   = smu + 32768;  // overlays WF
    float* sDilB = (float*)(smu + 49152);
    float* sResB = sDilB + 128;

    int tid = threadIdx.x, lane = tid & 31, warp = tid >> 5, tt = warp & 7, oh = warp >> 3;
    int t0 = blockIdx.x * 128, b = blockIdx.y;
    const float* xin = &g_x[par][b][0][0];
    float* xout = &g_x[par ^ 1][b][0][0];
    const float* dW = dilate_W + (size_t)l * 16384;  // [o][k][tap]

    stageA<512>(XcF, 8192, xin, t0, tid);
    stageA<512>(XpF, 8192, xin, t0 - d, tid);
    stageB<512>(WF, 8192, dW + 1, 128, 128, 2, tid);         // tap 1 (current)
    if (tid < 128) sDilB[tid] = dilate_b[l * N2R + tid];
    if (l < NL - 1 && tid < 64) sResB[tid] = res_b[l * 64 + tid];
    __syncthreads();

    float D[8][4] = {};
    mma_tile<8>(D, XcF, 8192, WF, 8192, tt, oh * 8, lane);
    __syncthreads();
    stageB<512>(WF, 8192, dW, 128, 128, 2, tid);             // tap 0 (prev)
    __syncthreads();
    mma_tile<8>(D, XpF, 8192, WF, 8192, tt, oh * 8, lane);
    __syncthreads();

    // epilogue 1: ia = D + bias -> out; a = ia + cond -> sAfull
    int g = lane >> 2, tg = lane & 3, tl1 = tt * 16 + g, t1 = t0 + tl1;
    size_t iab = ((size_t)(b * NL + l) * N2R) * TSEQ;
#pragma unroll
    for (int nt = 0; nt < 8; ++nt) {
        int o = oh * 64 + nt * 8 + tg * 2;
        size_t r0 = iab + (size_t)o * TSEQ + t1, r1 = r0 + TSEQ;
        float i00 = D[nt][0] + sDilB[o], i01 = D[nt][1] + sDilB[o + 1];
        float i10 = D[nt][2] + sDilB[o], i11 = D[nt][3] + sDilB[o + 1];
        ia_base[r0] = i00;     ia_base[r1] = i01;
        ia_base[r0 + 8] = i10; ia_base[r1 + 8] = i11;
        sAfull[o * 128 + tl1]           = i00 + cond_base[r0];
        sAfull[(o + 1) * 128 + tl1]     = i01 + cond_base[r1];
        sAfull[o * 128 + tl1 + 8]       = i10 + cond_base[r0 + 8];
        sAfull[(o + 1) * 128 + tl1 + 8] = i11 + cond_base[r1 + 8];
    }
    __syncthreads();

    // gate -> g_acts + A-frags; stage res weights
    for (int i = tid; i < 64 * 128; i += 512) {
        int r = i >> 7, tl = i & 127;
        float a1 = sAfull[r * 128 + tl], a2 = sAfull[(r + 64) * 128 + tl];
        float act = tanhf(a1) * (0.5f * tanhf(0.5f * a2) + 0.5f);
        g_acts[l][b][r][t0 + tl] = act;
        unsigned h = tf32r(act);
        int off = afrag(tl, r);
        ActsF[off] = h; ActsF[8192 + off] = tf32r(act - __uint_as_float(h));
    }
    if (l < NL - 1) stageB<512>(RWF, 4096, res_W + (size_t)l * 4096, 64, 64, 1, tid);
    __syncthreads();

    if (l < NL - 1) {
        float D3[4][4] = {};
        mma_tile<4>(D3, ActsF, 8192, RWF, 4096, tt, oh * 4, lane);
#pragma unroll
        for (int nt = 0; nt < 4; ++nt) {
            int r = oh * 32 + nt * 8 + tg * 2;
            size_t r0 = (size_t)r * TSEQ + t1, r1 = r0 + TSEQ;
            xout[r0]     = (D3[nt][0] + sResB[r]     + xin[r0])     * SQRT_HALF;
            xout[r1]     = (D3[nt][1] + sResB[r + 1] + xin[r1])     * SQRT_HALF;
            xout[r0 + 8] = (D3[nt][2] + sResB[r]     + xin[r0 + 8]) * SQRT_HALF;
            xout[r1 + 8] = (D3[nt][3] + sResB[r + 1] + xin[r1 + 8]) * SQRT_HALF;
        }
    }
}

// ---------------------------------------------------------------------------
__global__ void __launch_bounds__(512)
skip_kernel(const float* __restrict__ skip_W, const float* __restrict__ skip_b) {
    extern __shared__ unsigned smu[];
    unsigned* AF = smu;            // 16384
    unsigned* WF = smu + 16384;    // 32768
    float* sB = (float*)(smu + 49152);
    int tid = threadIdx.x, lane = tid & 31, warp = tid >> 5, tt = warp & 7, oh = warp >> 3;
    int t0 = blockIdx.x * 128, b = blockIdx.y;
    if (tid < 256) {
        float s = 0.f;
        for (int l = 0; l < NL; ++l) s += skip_b[l * NS + tid];
        sB[tid] = s;
    }
    float D[16][4] = {};
    for (int l = 0; l < NL; ++l) {
        __syncthreads();
        stageA<512>(AF, 8192, &g_acts[l][b][0][0], t0, tid);
        stageB<512>(WF, 16384, skip_W + (size_t)l * NS * 64, 256, 64, 1, tid);
        __syncthreads();
        mma_tile<16>(D, AF, 8192, WF, 16384, tt, oh * 16, lane);
    }
    int g = lane >> 2, tg = lane & 3, t1 = t0 + tt * 16 + g;
    float* h = &g_h1[0][0][0];
#pragma unroll
    for (int nt = 0; nt < 16; ++nt) {
        int o = oh * 128 + nt * 8 + tg * 2;
        size_t r0 = ((size_t)b * NS + o) * TSEQ + t1, r1 = r0 + TSEQ;
        h[r0] = fmaxf(D[nt][0] + sB[o], 0.f);     h[r1] = fmaxf(D[nt][1] + sB[o + 1], 0.f);
        h[r0 + 8] = fmaxf(D[nt][2] + sB[o], 0.f); h[r1 + 8] = fmaxf(D[nt][3] + sB[o + 1], 0.f);
    }
}

// ---------------------------------------------------------------------------
__global__ void __launch_bounds__(512)
mm_kernel(const float* __restrict__ Wmat, float* __restrict__ outp, int mode) {
    extern __shared__ unsigned smu[];
    unsigned* AF = smu;
    unsigned* WF = smu + 16384;
    int tid = threadIdx.x, lane = tid & 31, warp = tid >> 5, tt = warp & 7, oh = warp >> 3;
    int t0 = blockIdx.x * 128, b = blockIdx.y;
    const float* in = (mode == 0) ? &g_h1[b][0][0] : &g_h2[b][0][0];
    float D[16][4] = {};
    for (int ch = 0; ch < 4; ++ch) {
        __syncthreads();
        stageA<512>(AF, 8192, in + (size_t)ch * 64 * TSEQ, t0, tid);
        stageB<512>(WF, 16384, Wmat + ch * 64, 256, 256, 1, tid);
        __syncthreads();
        mma_tile<16>(D, AF, 8192, WF, 16384, tt, oh * 16, lane);
    }
    int g = lane >> 2, tg = lane & 3, t1 = t0 + tt * 16 + g;
#pragma unroll
    for (int nt = 0; nt < 16; ++nt) {
        int o = oh * 128 + nt * 8 + tg * 2;
        if (mode == 0) {
            float* h = &g_h2[0][0][0];
            size_t r0 = ((size_t)b * NS + o) * TSEQ + t1, r1 = r0 + TSEQ;
            h[r0] = fmaxf(D[nt][0], 0.f);     h[r1] = fmaxf(D[nt][1], 0.f);
            h[r0 + 8] = fmaxf(D[nt][2], 0.f); h[r1 + 8] = fmaxf(D[nt][3], 0.f);
        } else {
            size_t b0 = ((size_t)b * 256 + o) * TSEQ, b1 = b0 + TSEQ;
            int ta = t1 + 1, tb = t1 + 9;   // shift right by one
            if (ta < TSEQ) { outp[b0 + ta] = D[nt][0]; outp[b1 + ta] = D[nt][1]; }
            if (tb < TSEQ) { outp[b0 + tb] = D[nt][2]; outp[b1 + tb] = D[nt][3]; }
            if (t1 == 0) { outp[b0] = 0.f; outp[b1] = 0.f; }
        }
    }
}

// ---------------------------------------------------------------------------
extern "C" void kernel_launch(void* const* d_in, const int* in_sizes, int n_in,
                              void* d_out, int out_size) {
    const float* features   = (const float*)d_in[0];
    const int*   tokens     = (const int*)  d_in[1];
    const float* embed      = (const float*)d_in[2];
    const float* cond_W     = (const float*)d_in[3];
    const float* cond_b     = (const float*)d_in[4];
    const float* dilate_W   = (const float*)d_in[5];
    const float* dilate_b   = (const float*)d_in[6];
    const float* res_W      = (const float*)d_in[7];
    const float* res_b      = (const float*)d_in[8];
    const float* skip_W     = (const float*)d_in[9];
    const float* skip_b     = (const float*)d_in[10];
    const float* conv_out_W = (const float*)d_in[11];
    const float* conv_end_W = (const float*)d_in[12];

    float* outp      = (float*)d_out;                            // (B,256,T)
    float* ia_base   = outp + (size_t)TB * 256 * TSEQ;           // (B,L,128,T)
    float* cond_base = ia_base + (size_t)TB * NL * N2R * TSEQ;   // (B,L,128,T)

    static const int DILS[NL] = {1, 2, 4, 8, 16, 32, 64, 128, 256,
                                 1, 2, 4, 8, 16, 32, 64};

    cudaFuncSetAttribute(cond_kernel,  cudaFuncAttributeMaxDynamicSharedMemorySize, 132096);
    cudaFuncSetAttribute(layer_kernel, cudaFuncAttributeMaxDynamicSharedMemorySize, 198144);
    cudaFuncSetAttribute(skip_kernel,  cudaFuncAttributeMaxDynamicSharedMemorySize, 198656);
    cudaFuncSetAttribute(mm_kernel,    cudaFuncAttributeMaxDynamicSharedMemorySize, 196608);

    embed_kernel<<<dim3(TSEQ / 256, TB), 256>>>(tokens, embed);
    cond_kernel<<<dim3(TSEQ / 128, 16, TB), 512, 132096>>>(features, cond_W, cond_b, cond_base);

    for (int l = 0; l < NL; ++l)
        layer_kernel<<<dim3(TSEQ / 128, TB), 512, 198144>>>(
            dilate_W, dilate_b, res_W, res_b, cond_base, ia_base, l, DILS[l], l & 1);

    skip_kernel<<<dim3(TSEQ / 128, TB), 512, 198656>>>(skip_W, skip_b);
    mm_kernel<<<dim3(TSEQ / 128, TB), 512, 196608>>>(conv_out_W, nullptr, 0);
    mm_kernel<<<dim3(TSEQ / 128, TB), 512, 196608>>>(conv_end_W, outp, 1);
}